// round 11
// baseline (speedup 1.0000x reference)
#include <cuda_runtime.h>
#include <cuda_fp16.h>
#include <math.h>
#include <stdint.h>

// B=32, N=4096, D=512, K=64
#define Bb 32
#define Nn 4096
#define Dd 512
#define Kk 64
#define NSPLIT 2

__device__ float g_assign[(size_t)Bb * Nn * Kk];            // softmax assignments [b,n,k]
__device__ float g_vpart[(size_t)NSPLIT * Bb * Kk * Dd];    // vlad partials [s,b,k,d]
__device__ float g_asum[Bb * Kk];
__device__ float g_gnormsq[Bb];

// pack two floats -> half2 (lo, hi) as uint32
__device__ __forceinline__ uint32_t h2pack(float lo, float hi) {
    __half2 h = __floats2half2_rn(lo, hi);
    return *(uint32_t*)&h;
}

// fp16 HMMA m16n8k16, fp32 accumulate
__device__ __forceinline__ void mma16(float* c, uint32_t a0, uint32_t a1,
                                      uint32_t a2, uint32_t a3,
                                      uint32_t b0, uint32_t b1) {
    asm volatile(
        "mma.sync.aligned.m16n8k16.row.col.f32.f16.f16.f32 "
        "{%0,%1,%2,%3},{%4,%5,%6,%7},{%8,%9},{%0,%1,%2,%3};\n"
        : "+f"(c[0]), "+f"(c[1]), "+f"(c[2]), "+f"(c[3])
        : "r"(a0), "r"(a1), "r"(a2), "r"(a3), "r"(b0), "r"(b1));
}

// ---------------------------------------------------------------------------
__global__ void k0_init() {
    int i = blockIdx.x * 256 + threadIdx.x;
    if (i < Bb * Kk) g_asum[i] = 0.0f;
    if (i < Bb)      g_gnormsq[i] = 0.0f;
}

// ---------------------------------------------------------------------------
// k1: logits = x @ clusters (131072x512 @ 512x64) via fp16 MMA m16n8k16,
// fused BN(eval) + softmax + assignment store + a_sum atomic.
// Block: 256 thr (8 warps), tile 128 rows x 64 cols, K chunk 32 (2 ksteps).
// ---------------------------------------------------------------------------
__global__ __launch_bounds__(256, 3) void k1_logits_softmax(
    const float* __restrict__ x,
    const float* __restrict__ clusters,
    const float* __restrict__ bnw,
    const float* __restrict__ bnb,
    const float* __restrict__ rm,
    const float* __restrict__ rv)
{
    __shared__ uint32_t xs[128][20];   // frag-load bank = 20*la+lb : conflict-free
    __shared__ uint32_t cs[64][20];
    __shared__ float scf[64], shf[64];
    __shared__ float red[8 * 64];

    const int tid  = threadIdx.x;
    const int lane = tid & 31;
    const int w    = tid >> 5;
    const int la   = lane >> 2;     // 0..7
    const int lb   = lane & 3;      // 0..3
    const int row0 = blockIdx.x * 128;

    const int xr  = tid >> 1;
    const int xc4 = (tid & 1) * 16;
    const int cn = tid & 63;
    const int ck = (tid >> 6) * 4;

    const float* xg = x + (size_t)row0 * Dd;

    float acc[8][4];
#pragma unroll
    for (int j = 0; j < 8; j++)
#pragma unroll
        for (int q = 0; q < 4; q++) acc[j][q] = 0.0f;

    float4 px[4];
    float pcl[8];
#pragma unroll
    for (int q = 0; q < 4; q++)
        px[q] = *(const float4*)&xg[(size_t)xr * Dd + xc4 + q * 4];
#pragma unroll
    for (int g = 0; g < 4; g++) {
        pcl[2 * g]     = clusters[(size_t)(2 * (ck + g))     * Kk + cn];
        pcl[2 * g + 1] = clusters[(size_t)(2 * (ck + g) + 1) * Kk + cn];
    }

    for (int c = 0; c < 16; c++) {
#pragma unroll
        for (int q = 0; q < 4; q++) {
            xs[xr][(xc4 >> 1) + 2 * q]     = h2pack(px[q].x, px[q].y);
            xs[xr][(xc4 >> 1) + 2 * q + 1] = h2pack(px[q].z, px[q].w);
        }
#pragma unroll
        for (int g = 0; g < 4; g++)
            cs[cn][ck + g] = h2pack(pcl[2 * g], pcl[2 * g + 1]);
        __syncthreads();

        if (c < 15) {
            int d0 = (c + 1) * 32;
#pragma unroll
            for (int q = 0; q < 4; q++)
                px[q] = *(const float4*)&xg[(size_t)xr * Dd + d0 + xc4 + q * 4];
#pragma unroll
            for (int g = 0; g < 4; g++) {
                pcl[2 * g]     = clusters[(size_t)(d0 + 2 * (ck + g))     * Kk + cn];
                pcl[2 * g + 1] = clusters[(size_t)(d0 + 2 * (ck + g) + 1) * Kk + cn];
            }
        }

        const int wr = w * 16 + la;
#pragma unroll
        for (int s = 0; s < 2; s++) {
            uint32_t a0 = xs[wr][s * 8 + lb];
            uint32_t a1 = xs[wr + 8][s * 8 + lb];
            uint32_t a2 = xs[wr][s * 8 + 4 + lb];
            uint32_t a3 = xs[wr + 8][s * 8 + 4 + lb];
#pragma unroll
            for (int j = 0; j < 8; j++) {
                uint32_t b0 = cs[j * 8 + la][s * 8 + lb];
                uint32_t b1 = cs[j * 8 + la][s * 8 + 4 + lb];
                mma16(acc[j], a0, a1, a2, a3, b0, b1);
            }
        }
        __syncthreads();
    }

    // ---- epilogue: BN + softmax + store + a_sum ----
    if (tid < 64) {
        float istd = rsqrtf(rv[tid] + 1e-5f);
        float s = bnw[tid] * istd;
        scf[tid] = s;
        shf[tid] = bnb[tid] - rm[tid] * s;
    }
    __syncthreads();

    float vA[8][2], vB[8][2];
#pragma unroll
    for (int j = 0; j < 8; j++)
#pragma unroll
        for (int e = 0; e < 2; e++) {
            int col = j * 8 + lb * 2 + e;
            float s = scf[col], h = shf[col];
            vA[j][e] = acc[j][e]     * s + h;
            vB[j][e] = acc[j][2 + e] * s + h;
        }

    float mA = -1e30f, mB = -1e30f;
#pragma unroll
    for (int j = 0; j < 8; j++)
#pragma unroll
        for (int e = 0; e < 2; e++) { mA = fmaxf(mA, vA[j][e]); mB = fmaxf(mB, vB[j][e]); }
    mA = fmaxf(mA, __shfl_xor_sync(0xffffffffu, mA, 1));
    mA = fmaxf(mA, __shfl_xor_sync(0xffffffffu, mA, 2));
    mB = fmaxf(mB, __shfl_xor_sync(0xffffffffu, mB, 1));
    mB = fmaxf(mB, __shfl_xor_sync(0xffffffffu, mB, 2));
    float sA = 0.0f, sB = 0.0f;
#pragma unroll
    for (int j = 0; j < 8; j++)
#pragma unroll
        for (int e = 0; e < 2; e++) {
            vA[j][e] = __expf(vA[j][e] - mA); sA += vA[j][e];
            vB[j][e] = __expf(vB[j][e] - mB); sB += vB[j][e];
        }
    sA += __shfl_xor_sync(0xffffffffu, sA, 1);
    sA += __shfl_xor_sync(0xffffffffu, sA, 2);
    sB += __shfl_xor_sync(0xffffffffu, sB, 1);
    sB += __shfl_xor_sync(0xffffffffu, sB, 2);
    float invA = 1.0f / sA, invB = 1.0f / sB;

    float csum[8][2];
    const int grA = row0 + w * 16 + la;
    const int grB = grA + 8;
    float* ag = g_assign;
#pragma unroll
    for (int j = 0; j < 8; j++) {
#pragma unroll
        for (int e = 0; e < 2; e++) {
            vA[j][e] *= invA;
            vB[j][e] *= invB;
            csum[j][e] = vA[j][e] + vB[j][e];
        }
        *(float2*)&ag[(size_t)grA * Kk + j * 8 + lb * 2] = make_float2(vA[j][0], vA[j][1]);
        *(float2*)&ag[(size_t)grB * Kk + j * 8 + lb * 2] = make_float2(vB[j][0], vB[j][1]);
    }

#pragma unroll
    for (int j = 0; j < 8; j++)
#pragma unroll
        for (int e = 0; e < 2; e++) {
            csum[j][e] += __shfl_xor_sync(0xffffffffu, csum[j][e], 4);
            csum[j][e] += __shfl_xor_sync(0xffffffffu, csum[j][e], 8);
            csum[j][e] += __shfl_xor_sync(0xffffffffu, csum[j][e], 16);
        }
    if (la == 0) {
#pragma unroll
        for (int j = 0; j < 8; j++)
#pragma unroll
            for (int e = 0; e < 2; e++)
                red[w * 64 + j * 8 + lb * 2 + e] = csum[j][e];
    }
    __syncthreads();
    if (tid < 64) {
        float s = 0.0f;
#pragma unroll
        for (int q = 0; q < 8; q++) s += red[q * 64 + tid];
        atomicAdd(&g_asum[(row0 >> 12) * Kk + tid], s);
    }
}

// ---------------------------------------------------------------------------
// k2: vlad partials via fp16 MMA. A = x^T [d][n-pairs], B = assign^T [k][n-pairs].
// Block: 128 thr (4 warps), tile d=64 x k=64, n-chunk 32, NSPLIT=2.
// ---------------------------------------------------------------------------
__global__ __launch_bounds__(128, 6) void k2_vlad(const float* __restrict__ x)
{
    __shared__ uint32_t xs[64][20];   // [d][n-granule]
    __shared__ uint32_t as[64][20];   // [k][n-granule]

    const int tid  = threadIdx.x;
    const int lane = tid & 31;
    const int w    = tid >> 5;
    const int la   = lane >> 2;
    const int lb   = lane & 3;
    const int b    = blockIdx.y;
    const int d0   = blockIdx.x * 64;
    const int s    = blockIdx.z;
    const int nbase = s * (Nn / NSPLIT);

    const int nn = tid & 15;
    const int sg = (tid >> 4) * 8;

    const float* xg = x + ((size_t)b * Nn + nbase) * Dd + d0;
    const float* ag = g_assign + ((size_t)b * Nn + nbase) * Kk;

    float acc[8][4];
#pragma unroll
    for (int j = 0; j < 8; j++)
#pragma unroll
        for (int q = 0; q < 4; q++) acc[j][q] = 0.0f;

    float4 pxl[2], pxh[2], pal[2], pah[2];
#pragma unroll
    for (int q = 0; q < 2; q++) {
        pxl[q] = *(const float4*)&xg[(size_t)(2 * nn)     * Dd + sg + q * 4];
        pxh[q] = *(const float4*)&xg[(size_t)(2 * nn + 1) * Dd + sg + q * 4];
        pal[q] = *(const float4*)&ag[(size_t)(2 * nn)     * Kk + sg + q * 4];
        pah[q] = *(const float4*)&ag[(size_t)(2 * nn + 1) * Kk + sg + q * 4];
    }

    for (int c = 0; c < Nn / NSPLIT / 32; c++) {
        {
            float xl[8] = { pxl[0].x, pxl[0].y, pxl[0].z, pxl[0].w,
                            pxl[1].x, pxl[1].y, pxl[1].z, pxl[1].w };
            float xh[8] = { pxh[0].x, pxh[0].y, pxh[0].z, pxh[0].w,
                            pxh[1].x, pxh[1].y, pxh[1].z, pxh[1].w };
            float al[8] = { pal[0].x, pal[0].y, pal[0].z, pal[0].w,
                            pal[1].x, pal[1].y, pal[1].z, pal[1].w };
            float ah[8] = { pah[0].x, pah[0].y, pah[0].z, pah[0].w,
                            pah[1].x, pah[1].y, pah[1].z, pah[1].w };
#pragma unroll
            for (int e = 0; e < 8; e++) {
                xs[sg + e][nn] = h2pack(xl[e], xh[e]);
                as[sg + e][nn] = h2pack(al[e], ah[e]);
            }
        }
        __syncthreads();

        if (c < Nn / NSPLIT / 32 - 1) {
            int n0 = (c + 1) * 32;
#pragma unroll
            for (int q = 0; q < 2; q++) {
                pxl[q] = *(const float4*)&xg[(size_t)(n0 + 2 * nn)     * Dd + sg + q * 4];
                pxh[q] = *(const float4*)&xg[(size_t)(n0 + 2 * nn + 1) * Dd + sg + q * 4];
                pal[q] = *(const float4*)&ag[(size_t)(n0 + 2 * nn)     * Kk + sg + q * 4];
                pah[q] = *(const float4*)&ag[(size_t)(n0 + 2 * nn + 1) * Kk + sg + q * 4];
            }
        }

        const int wr = w * 16 + la;
#pragma unroll
        for (int ss = 0; ss < 2; ss++) {
            uint32_t a0 = xs[wr][ss * 8 + lb];
            uint32_t a1 = xs[wr + 8][ss * 8 + lb];
            uint32_t a2 = xs[wr][ss * 8 + 4 + lb];
            uint32_t a3 = xs[wr + 8][ss * 8 + 4 + lb];
#pragma unroll
            for (int j = 0; j < 8; j++) {
                uint32_t b0 = as[j * 8 + la][ss * 8 + lb];
                uint32_t b1 = as[j * 8 + la][ss * 8 + 4 + lb];
                mma16(acc[j], a0, a1, a2, a3, b0, b1);
            }
        }
        __syncthreads();
    }

    float* vp = g_vpart + ((size_t)s * Bb + b) * Kk * Dd;
    const int gdA = d0 + w * 16 + la;
    const int gdB = gdA + 8;
#pragma unroll
    for (int j = 0; j < 8; j++)
#pragma unroll
        for (int e = 0; e < 2; e++) {
            int col = j * 8 + lb * 2 + e;
            vp[(size_t)col * Dd + gdA] = acc[j][e];
            vp[(size_t)col * Dd + gdB] = acc[j][2 + e];
        }
}

// ---------------------------------------------------------------------------
__global__ __launch_bounds__(128) void k3_colnorm(const float* __restrict__ c2,
                                                  float* __restrict__ out)
{
    const int bk = blockIdx.x;
    const int b = bk >> 6;
    const int k = bk & 63;
    const int tid = threadIdx.x;
    const size_t SP = (size_t)Bb * Kk * Dd;

    const float a = g_asum[bk];
    const float* vr = g_vpart + (size_t)bk * Dd;

    float v[4];
    float ss = 0.0f;
#pragma unroll
    for (int p = 0; p < 4; p++) {
        int d = tid + p * 128;
        float t = vr[d] + vr[d + SP] - a * c2[(size_t)d * Kk + k];
        v[p] = t;
        ss += t * t;
    }
#pragma unroll
    for (int o = 16; o; o >>= 1) ss += __shfl_xor_sync(0xffffffffu, ss, o);

    __shared__ float sred[4];
    if ((tid & 31) == 0) sred[tid >> 5] = ss;
    __syncthreads();
    float tot = sred[0] + sred[1] + sred[2] + sred[3];
    float inv = 1.0f / fmaxf(sqrtf(tot), 1e-12f);
    if (tid == 0) atomicAdd(&g_gnormsq[b], tot * inv * inv);

    float* ob = out + (size_t)b * (Dd * Kk);
#pragma unroll
    for (int p = 0; p < 4; p++) {
        int d = tid + p * 128;
        ob[(size_t)d * Kk + k] = v[p] * inv;
    }
}

// ---------------------------------------------------------------------------
__global__ void k4_scale(float* __restrict__ out)
{
    int idx = blockIdx.x * 256 + threadIdx.x;
    int b = idx >> 15;
    out[idx] *= 1.0f / fmaxf(sqrtf(g_gnormsq[b]), 1e-12f);
}

// ---------------------------------------------------------------------------
extern "C" void kernel_launch(void* const* d_in, const int* in_sizes, int n_in,
                              void* d_out, int out_size)
{
    const float* x        = (const float*)d_in[0];
    const float* clusters = (const float*)d_in[1];
    const float* c2       = (const float*)d_in[2];
    const float* bnw      = (const float*)d_in[3];
    const float* bnb      = (const float*)d_in[4];
    const float* rm       = (const float*)d_in[5];
    const float* rv       = (const float*)d_in[6];
    float* out = (float*)d_out;

    k0_init<<<8, 256>>>();
    k1_logits_softmax<<<(Bb * Nn) / 128, 256>>>(x, clusters, bnw, bnb, rm, rv);
    dim3 g2(Dd / 64, Bb, NSPLIT);
    k2_vlad<<<g2, 128>>>(x);
    k3_colnorm<<<Bb * Kk, 128>>>(c2, out);
    k4_scale<<<(Bb * Dd * Kk) / 256, 256>>>(out);
}

// round 12
// speedup vs baseline: 1.5613x; 1.5613x over previous
#include <cuda_runtime.h>
#include <cuda_fp16.h>
#include <math.h>
#include <stdint.h>

// B=32, N=4096, D=512, K=64
#define Bb 32
#define Nn 4096
#define Dd 512
#define Kk 64
#define NSPLIT 2

__device__ __half g_xh[(size_t)Bb * Nn * Dd];              // x as half, [n][d]
__device__ __half g_xth[(size_t)Bb * Dd * Nn];             // x as half, [b][d][n]
__device__ __half g_ch[(size_t)Kk * Dd];                   // clusters^T half [k][d]
__device__ __half g_ah[(size_t)Bb * Kk * Nn];              // assignment^T half [b][k][n]
__device__ float  g_vpart[(size_t)NSPLIT * Bb * Kk * Dd];  // vlad partials [s,b,k,d]
__device__ float  g_asum[Bb * Kk];
__device__ float  g_gnormsq[Bb];

__device__ __forceinline__ uint32_t h2pack(float lo, float hi) {
    __half2 h = __floats2half2_rn(lo, hi);
    return *(uint32_t*)&h;
}

__device__ __forceinline__ void mma16(float* c, uint32_t a0, uint32_t a1,
                                      uint32_t a2, uint32_t a3,
                                      uint32_t b0, uint32_t b1) {
    asm volatile(
        "mma.sync.aligned.m16n8k16.row.col.f32.f16.f16.f32 "
        "{%0,%1,%2,%3},{%4,%5,%6,%7},{%8,%9},{%0,%1,%2,%3};\n"
        : "+f"(c[0]), "+f"(c[1]), "+f"(c[2]), "+f"(c[3])
        : "r"(a0), "r"(a1), "r"(a2), "r"(a3), "r"(b0), "r"(b1));
}

__device__ __forceinline__ uint32_t smem_u32(const void* p) {
    uint32_t a;
    asm("{ .reg .u64 t; cvta.to.shared.u64 t, %1; cvt.u32.u64 %0, t; }"
        : "=r"(a) : "l"(p));
    return a;
}

#define CP16(dst, src) \
    asm volatile("cp.async.cg.shared.global [%0], [%1], 16;\n" \
                 :: "r"(dst), "l"(src) : "memory")
#define CP_COMMIT() asm volatile("cp.async.commit_group;\n" ::: "memory")
#define CP_WAIT2()  asm volatile("cp.async.wait_group 2;\n" ::: "memory")

// ---------------------------------------------------------------------------
__global__ void k0_init() {
    int i = blockIdx.x * 256 + threadIdx.x;
    if (i < Bb * Kk) g_asum[i] = 0.0f;
    if (i < Bb)      g_gnormsq[i] = 0.0f;
}

// ---------------------------------------------------------------------------
// kC: clusters [d][k] fp32 -> g_ch [k][d] half
// ---------------------------------------------------------------------------
__global__ __launch_bounds__(256) void kC(const float* __restrict__ clusters) {
    int idx4 = (blockIdx.x * 256 + threadIdx.x) * 4;   // 32 blocks cover 32768
    int d = idx4 >> 6, k = idx4 & 63;
    float4 c = *(const float4*)&clusters[idx4];
    g_ch[(size_t)(k + 0) * Dd + d] = __float2half_rn(c.x);
    g_ch[(size_t)(k + 1) * Dd + d] = __float2half_rn(c.y);
    g_ch[(size_t)(k + 2) * Dd + d] = __float2half_rn(c.z);
    g_ch[(size_t)(k + 3) * Dd + d] = __float2half_rn(c.w);
}

// ---------------------------------------------------------------------------
// kP: x fp32 [b][n][d] -> g_xh half [n][d]  AND  g_xth half [b][d][n]
// Block: 64n x 64d tile, 256 threads. Grid (8 d-tiles, 64 n-tiles, 32 b).
// ---------------------------------------------------------------------------
__global__ __launch_bounds__(256) void kP(const float* __restrict__ x) {
    __shared__ __half hs[64 * 74];
    const int t  = threadIdx.x;
    const int d0 = blockIdx.x * 64, n0 = blockIdx.y * 64, b = blockIdx.z;

    const float* xb = x + ((size_t)b * Nn + n0) * Dd + d0;
    const int i  = t >> 2;           // n row 0..63
    const int j0 = (t & 3) * 16;     // d seg

    float4 v[4];
#pragma unroll
    for (int q = 0; q < 4; q++)
        v[q] = *(const float4*)&xb[(size_t)i * Dd + j0 + q * 4];

    uint32_t wv[8];
#pragma unroll
    for (int q = 0; q < 4; q++) {
        wv[2 * q]     = h2pack(v[q].x, v[q].y);
        wv[2 * q + 1] = h2pack(v[q].z, v[q].w);
    }
    // xh [n][d]
    __half* xhp = g_xh + ((size_t)(b * Nn + n0 + i)) * Dd + d0 + j0;
    *(uint4*)xhp       = make_uint4(wv[0], wv[1], wv[2], wv[3]);
    *(uint4*)(xhp + 8) = make_uint4(wv[4], wv[5], wv[6], wv[7]);
    // smem tile [n][d]
#pragma unroll
    for (int q = 0; q < 8; q++)
        *(uint32_t*)&hs[i * 74 + j0 + q * 2] = wv[q];
    __syncthreads();

    // xTh [d][n]
    const int dl = t >> 2, ns = (t & 3) * 16;
    const uint16_t* h16 = (const uint16_t*)hs;
    uint32_t o[8];
#pragma unroll
    for (int q = 0; q < 8; q++) {
        uint32_t lo = h16[(ns + 2 * q)     * 74 + dl];
        uint32_t hi = h16[(ns + 2 * q + 1) * 74 + dl];
        o[q] = lo | (hi << 16);
    }
    __half* dst = g_xth + ((size_t)(b * Dd + d0 + dl)) * Nn + n0 + ns;
    *(uint4*)dst       = make_uint4(o[0], o[1], o[2], o[3]);
    *(uint4*)(dst + 8) = make_uint4(o[4], o[5], o[6], o[7]);
}

// ---------------------------------------------------------------------------
// k1: logits GEMM + BN + softmax + assignment^T(half) + a_sum.
// 256 thr, tile 128n x 64k, K chunk 32, 3-stage cp.async pipeline.
// smem: 3 stages x (xs 128x80B + cs 64x80B) + scf/shf + red. hbuf overlays.
// ---------------------------------------------------------------------------
#define K1_ST   15360
#define K1_CSO  10240
#define K1_SCF  46080
#define K1_SHF  46336
#define K1_RED  46592
#define K1_SMEM 48640

__device__ __forceinline__ void k1_issue(uint32_t sbase, const __half* xh,
                                         int c, int tid) {
    if (c < 16) {
        uint32_t st = sbase + (c % 3) * K1_ST;
        int d0 = c * 32;
#pragma unroll
        for (int p = 0; p < 2; p++) {
            int id = p * 256 + tid;
            int row = id >> 2, sq = id & 3;
            CP16(st + row * 80 + sq * 16, xh + (size_t)row * Dd + d0 + sq * 8);
        }
        {
            int row = tid >> 2, sq = tid & 3;
            CP16(st + K1_CSO + row * 80 + sq * 16,
                 g_ch + (size_t)row * Dd + d0 + sq * 8);
        }
    }
    CP_COMMIT();
}

__global__ __launch_bounds__(256) void k1_logits_softmax(
    const float* __restrict__ bnw,
    const float* __restrict__ bnb,
    const float* __restrict__ rm,
    const float* __restrict__ rv)
{
    extern __shared__ __align__(16) char sm[];
    float* scf = (float*)(sm + K1_SCF);
    float* shf = (float*)(sm + K1_SHF);
    float* red = (float*)(sm + K1_RED);
    const uint32_t sbase = smem_u32(sm);

    const int tid  = threadIdx.x;
    const int lane = tid & 31;
    const int w    = tid >> 5;
    const int la   = lane >> 2;
    const int lb   = lane & 3;
    const int row0 = blockIdx.x * 128;

    if (tid < 64) {
        float istd = rsqrtf(rv[tid] + 1e-5f);
        float s = bnw[tid] * istd;
        scf[tid] = s;
        shf[tid] = bnb[tid] - rm[tid] * s;
    }

    const __half* xh = g_xh + (size_t)row0 * Dd;

    float acc[8][4];
#pragma unroll
    for (int j = 0; j < 8; j++)
#pragma unroll
        for (int q = 0; q < 4; q++) acc[j][q] = 0.0f;

    k1_issue(sbase, xh, 0, tid);
    k1_issue(sbase, xh, 1, tid);

    const int wr = w * 16 + la;
    for (int c = 0; c < 16; c++) {
        __syncthreads();
        k1_issue(sbase, xh, c + 2, tid);
        CP_WAIT2();
        __syncthreads();

        const uint32_t* xsA = (const uint32_t*)(sm + (c % 3) * K1_ST);
        const uint32_t* csA = (const uint32_t*)(sm + (c % 3) * K1_ST + K1_CSO);
#pragma unroll
        for (int s = 0; s < 2; s++) {
            uint32_t a0 = xsA[wr * 20 + s * 8 + lb];
            uint32_t a1 = xsA[(wr + 8) * 20 + s * 8 + lb];
            uint32_t a2 = xsA[wr * 20 + s * 8 + 4 + lb];
            uint32_t a3 = xsA[(wr + 8) * 20 + s * 8 + 4 + lb];
#pragma unroll
            for (int j = 0; j < 8; j++) {
                uint32_t b0 = csA[(j * 8 + la) * 20 + s * 8 + lb];
                uint32_t b1 = csA[(j * 8 + la) * 20 + s * 8 + 4 + lb];
                mma16(acc[j], a0, a1, a2, a3, b0, b1);
            }
        }
    }
    __syncthreads();

    // ---- BN + softmax (fp32, identical to R10) ----
    float vA[8][2], vB[8][2];
#pragma unroll
    for (int j = 0; j < 8; j++)
#pragma unroll
        for (int e = 0; e < 2; e++) {
            int col = j * 8 + lb * 2 + e;
            float s = scf[col], h = shf[col];
            vA[j][e] = acc[j][e]     * s + h;
            vB[j][e] = acc[j][2 + e] * s + h;
        }

    float mA = -1e30f, mB = -1e30f;
#pragma unroll
    for (int j = 0; j < 8; j++)
#pragma unroll
        for (int e = 0; e < 2; e++) { mA = fmaxf(mA, vA[j][e]); mB = fmaxf(mB, vB[j][e]); }
    mA = fmaxf(mA, __shfl_xor_sync(0xffffffffu, mA, 1));
    mA = fmaxf(mA, __shfl_xor_sync(0xffffffffu, mA, 2));
    mB = fmaxf(mB, __shfl_xor_sync(0xffffffffu, mB, 1));
    mB = fmaxf(mB, __shfl_xor_sync(0xffffffffu, mB, 2));
    float sA = 0.0f, sB = 0.0f;
#pragma unroll
    for (int j = 0; j < 8; j++)
#pragma unroll
        for (int e = 0; e < 2; e++) {
            vA[j][e] = __expf(vA[j][e] - mA); sA += vA[j][e];
            vB[j][e] = __expf(vB[j][e] - mB); sB += vB[j][e];
        }
    sA += __shfl_xor_sync(0xffffffffu, sA, 1);
    sA += __shfl_xor_sync(0xffffffffu, sA, 2);
    sB += __shfl_xor_sync(0xffffffffu, sB, 1);
    sB += __shfl_xor_sync(0xffffffffu, sB, 2);
    float invA = 1.0f / sA, invB = 1.0f / sB;

    float csum[8][2];
#pragma unroll
    for (int j = 0; j < 8; j++)
#pragma unroll
        for (int e = 0; e < 2; e++) {
            vA[j][e] *= invA;
            vB[j][e] *= invB;
            csum[j][e] = vA[j][e] + vB[j][e];
        }

    // a_sum reduction (identical to R10)
#pragma unroll
    for (int j = 0; j < 8; j++)
#pragma unroll
        for (int e = 0; e < 2; e++) {
            csum[j][e] += __shfl_xor_sync(0xffffffffu, csum[j][e], 4);
            csum[j][e] += __shfl_xor_sync(0xffffffffu, csum[j][e], 8);
            csum[j][e] += __shfl_xor_sync(0xffffffffu, csum[j][e], 16);
        }
    if (la == 0) {
#pragma unroll
        for (int j = 0; j < 8; j++)
#pragma unroll
            for (int e = 0; e < 2; e++)
                red[w * 64 + j * 8 + lb * 2 + e] = csum[j][e];
    }
    __syncthreads();
    if (tid < 64) {
        float s = 0.0f;
#pragma unroll
        for (int q = 0; q < 8; q++) s += red[q * 64 + tid];
        atomicAdd(&g_asum[(row0 >> 12) * Kk + tid], s);
    }

    // ---- write g_ah[b][k][n] via smem transpose (2 passes of 64 n) ----
    uint16_t* hb = (uint16_t*)sm;       // 64 x 74 halves, overlays stage smem
    const int bb  = row0 >> 12;
    const int r0n = row0 & (Nn - 1);
#pragma unroll
    for (int p = 0; p < 2; p++) {
        __syncthreads();
        if ((w >> 2) == p) {
            int wl = w & 3;
            int lA = wl * 16 + la, lB = lA + 8;
#pragma unroll
            for (int j = 0; j < 8; j++) {
                *(uint32_t*)&hb[lA * 74 + j * 8 + lb * 2] = h2pack(vA[j][0], vA[j][1]);
                *(uint32_t*)&hb[lB * 74 + j * 8 + lb * 2] = h2pack(vB[j][0], vB[j][1]);
            }
        }
        __syncthreads();
        int k = tid >> 2, sg2 = tid & 3;
        uint32_t o[8];
#pragma unroll
        for (int q = 0; q < 8; q++) {
            uint32_t lo = hb[(sg2 * 16 + 2 * q)     * 74 + k];
            uint32_t hi = hb[(sg2 * 16 + 2 * q + 1) * 74 + k];
            o[q] = lo | (hi << 16);
        }
        __half* dst = g_ah + ((size_t)(bb * Kk + k)) * Nn + r0n + p * 64 + sg2 * 16;
        *(uint4*)dst       = make_uint4(o[0], o[1], o[2], o[3]);
        *(uint4*)(dst + 8) = make_uint4(o[4], o[5], o[6], o[7]);
    }
}

// ---------------------------------------------------------------------------
// k2: vlad partials. A = xTh rows [d][n], B = g_ah rows [k][n] (both half,
// coalesced 64B rows). 128 thr, tile 64d x 64k, n-chunk 32, 3-stage cp.async.
// ---------------------------------------------------------------------------
#define K2_ST   10240
#define K2_ASO  5120
#define K2_SMEM 30720

__device__ __forceinline__ void k2_issue(uint32_t sbase, const __half* xr,
                                         const __half* ar, int c, int tid) {
    if (c < Nn / NSPLIT / 32) {
        uint32_t st = sbase + (c % 3) * K2_ST;
        int n0 = c * 32;
#pragma unroll
        for (int p = 0; p < 2; p++) {
            int id = p * 128 + tid;
            int row = id >> 2, sq = id & 3;
            CP16(st + row * 80 + sq * 16, xr + (size_t)row * Nn + n0 + sq * 8);
            CP16(st + K2_ASO + row * 80 + sq * 16,
                 ar + (size_t)row * Nn + n0 + sq * 8);
        }
    }
    CP_COMMIT();
}

__global__ __launch_bounds__(128) void k2_vlad()
{
    extern __shared__ __align__(16) char sm[];
    const uint32_t sbase = smem_u32(sm);

    const int tid  = threadIdx.x;
    const int lane = tid & 31;
    const int w    = tid >> 5;
    const int la   = lane >> 2;
    const int lb   = lane & 3;
    const int b    = blockIdx.y;
    const int d0   = blockIdx.x * 64;
    const int s    = blockIdx.z;
    const int nbase = s * (Nn / NSPLIT);

    const __half* xr = g_xth + ((size_t)(b * Dd + d0)) * Nn + nbase;
    const __half* ar = g_ah  + ((size_t)(b * Kk)) * Nn + nbase;

    float acc[8][4];
#pragma unroll
    for (int j = 0; j < 8; j++)
#pragma unroll
        for (int q = 0; q < 4; q++) acc[j][q] = 0.0f;

    k2_issue(sbase, xr, ar, 0, tid);
    k2_issue(sbase, xr, ar, 1, tid);

    const int wr = w * 16 + la;
    const int L = Nn / NSPLIT / 32;
    for (int c = 0; c < L; c++) {
        __syncthreads();
        k2_issue(sbase, xr, ar, c + 2, tid);
        CP_WAIT2();
        __syncthreads();

        const uint32_t* xsA = (const uint32_t*)(sm + (c % 3) * K2_ST);
        const uint32_t* asA = (const uint32_t*)(sm + (c % 3) * K2_ST + K2_ASO);
#pragma unroll
        for (int ss = 0; ss < 2; ss++) {
            uint32_t a0 = xsA[wr * 20 + ss * 8 + lb];
            uint32_t a1 = xsA[(wr + 8) * 20 + ss * 8 + lb];
            uint32_t a2 = xsA[wr * 20 + ss * 8 + 4 + lb];
            uint32_t a3 = xsA[(wr + 8) * 20 + ss * 8 + 4 + lb];
#pragma unroll
            for (int j = 0; j < 8; j++) {
                uint32_t b0 = asA[(j * 8 + la) * 20 + ss * 8 + lb];
                uint32_t b1 = asA[(j * 8 + la) * 20 + ss * 8 + 4 + lb];
                mma16(acc[j], a0, a1, a2, a3, b0, b1);
            }
        }
    }

    float* vp = g_vpart + ((size_t)s * Bb + b) * Kk * Dd;
    const int gdA = d0 + w * 16 + la;
    const int gdB = gdA + 8;
#pragma unroll
    for (int j = 0; j < 8; j++)
#pragma unroll
        for (int e = 0; e < 2; e++) {
            int col = j * 8 + lb * 2 + e;
            vp[(size_t)col * Dd + gdA] = acc[j][e];
            vp[(size_t)col * Dd + gdB] = acc[j][2 + e];
        }
}

// ---------------------------------------------------------------------------
__global__ __launch_bounds__(128) void k3_colnorm(const float* __restrict__ c2,
                                                  float* __restrict__ out)
{
    const int bk = blockIdx.x;
    const int b = bk >> 6;
    const int k = bk & 63;
    const int tid = threadIdx.x;
    const size_t SP = (size_t)Bb * Kk * Dd;

    const float a = g_asum[bk];
    const float* vr = g_vpart + (size_t)bk * Dd;

    float v[4];
    float ss = 0.0f;
#pragma unroll
    for (int p = 0; p < 4; p++) {
        int d = tid + p * 128;
        float t = vr[d] + vr[d + SP] - a * c2[(size_t)d * Kk + k];
        v[p] = t;
        ss += t * t;
    }
#pragma unroll
    for (int o = 16; o; o >>= 1) ss += __shfl_xor_sync(0xffffffffu, ss, o);

    __shared__ float sred[4];
    if ((tid & 31) == 0) sred[tid >> 5] = ss;
    __syncthreads();
    float tot = sred[0] + sred[1] + sred[2] + sred[3];
    float inv = 1.0f / fmaxf(sqrtf(tot), 1e-12f);
    if (tid == 0) atomicAdd(&g_gnormsq[b], tot * inv * inv);

    float* ob = out + (size_t)b * (Dd * Kk);
#pragma unroll
    for (int p = 0; p < 4; p++) {
        int d = tid + p * 128;
        ob[(size_t)d * Kk + k] = v[p] * inv;
    }
}

// ---------------------------------------------------------------------------
__global__ void k4_scale(float* __restrict__ out)
{
    int idx = blockIdx.x * 256 + threadIdx.x;
    int b = idx >> 15;
    out[idx] *= 1.0f / fmaxf(sqrtf(g_gnormsq[b]), 1e-12f);
}

// ---------------------------------------------------------------------------
extern "C" void kernel_launch(void* const* d_in, const int* in_sizes, int n_in,
                              void* d_out, int out_size)
{
    const float* x        = (const float*)d_in[0];
    const float* clusters = (const float*)d_in[1];
    const float* c2       = (const float*)d_in[2];
    const float* bnw      = (const float*)d_in[3];
    const float* bnb      = (const float*)d_in[4];
    const float* rm       = (const float*)d_in[5];
    const float* rv       = (const float*)d_in[6];
    float* out = (float*)d_out;

    k0_init<<<8, 256>>>();
    kC<<<32, 256>>>(clusters);
    dim3 gp(Dd / 64, Nn / 64, Bb);
    kP<<<gp, 256>>>(x);
    k1_logits_softmax<<<(Bb * Nn) / 128, 256, K1_SMEM>>>(bnw, bnb, rm, rv);
    dim3 g2(Dd / 64, Bb, NSPLIT);
    k2_vlad<<<g2, 128, K2_SMEM>>>();
    k3_colnorm<<<Bb * Kk, 128>>>(c2, out);
    k4_scale<<<(Bb * Dd * Kk) / 256, 256>>>(out);
}

// round 13
// speedup vs baseline: 1.9001x; 1.2170x over previous
#include <cuda_runtime.h>
#include <cuda_fp16.h>
#include <math.h>
#include <stdint.h>

// B=32, N=4096, D=512, K=64
#define Bb 32
#define Nn 4096
#define Dd 512
#define Kk 64
#define NSPLIT 2

__device__ __half g_xh[(size_t)Bb * Nn * Dd];              // x as half, [n][d]
__device__ __half g_ch[(size_t)Kk * Dd];                   // clusters^T half [k][d]
__device__ __half g_ah[(size_t)Bb * Kk * Nn];              // assignment^T half [b][k][n]
__device__ float  g_vpart[(size_t)NSPLIT * Bb * Kk * Dd];  // vlad partials [s,b,k,d]
__device__ float  g_asum[Bb * Kk];
__device__ float  g_gnormsq[Bb];

__device__ __forceinline__ uint32_t h2pack(float lo, float hi) {
    __half2 h = __floats2half2_rn(lo, hi);
    return *(uint32_t*)&h;
}

__device__ __forceinline__ void mma16(float* c, uint32_t a0, uint32_t a1,
                                      uint32_t a2, uint32_t a3,
                                      uint32_t b0, uint32_t b1) {
    asm volatile(
        "mma.sync.aligned.m16n8k16.row.col.f32.f16.f16.f32 "
        "{%0,%1,%2,%3},{%4,%5,%6,%7},{%8,%9},{%0,%1,%2,%3};\n"
        : "+f"(c[0]), "+f"(c[1]), "+f"(c[2]), "+f"(c[3])
        : "r"(a0), "r"(a1), "r"(a2), "r"(a3), "r"(b0), "r"(b1));
}

__device__ __forceinline__ void ldsm4t(uint32_t& r0, uint32_t& r1,
                                       uint32_t& r2, uint32_t& r3, uint32_t a) {
    asm volatile(
        "ldmatrix.sync.aligned.m8n8.x4.trans.shared.b16 {%0,%1,%2,%3}, [%4];"
        : "=r"(r0), "=r"(r1), "=r"(r2), "=r"(r3) : "r"(a));
}

__device__ __forceinline__ uint32_t smem_u32(const void* p) {
    uint32_t a;
    asm("{ .reg .u64 t; cvta.to.shared.u64 t, %1; cvt.u32.u64 %0, t; }"
        : "=r"(a) : "l"(p));
    return a;
}

#define CP16(dst, src) \
    asm volatile("cp.async.cg.shared.global [%0], [%1], 16;\n" \
                 :: "r"(dst), "l"(src) : "memory")
#define CP_COMMIT() asm volatile("cp.async.commit_group;\n" ::: "memory")
#define CP_WAIT2()  asm volatile("cp.async.wait_group 2;\n" ::: "memory")

// ---------------------------------------------------------------------------
__global__ void k0_init() {
    int i = blockIdx.x * 256 + threadIdx.x;
    if (i < Bb * Kk) g_asum[i] = 0.0f;
    if (i < Bb)      g_gnormsq[i] = 0.0f;
}

// ---------------------------------------------------------------------------
// kC: clusters [d][k] fp32 -> g_ch [k][d] half
// ---------------------------------------------------------------------------
__global__ __launch_bounds__(256) void kC(const float* __restrict__ clusters) {
    int idx4 = (blockIdx.x * 256 + threadIdx.x) * 4;   // 32 blocks cover 32768
    int d = idx4 >> 6, k = idx4 & 63;
    float4 c = *(const float4*)&clusters[idx4];
    g_ch[(size_t)(k + 0) * Dd + d] = __float2half_rn(c.x);
    g_ch[(size_t)(k + 1) * Dd + d] = __float2half_rn(c.y);
    g_ch[(size_t)(k + 2) * Dd + d] = __float2half_rn(c.z);
    g_ch[(size_t)(k + 3) * Dd + d] = __float2half_rn(c.w);
}

// ---------------------------------------------------------------------------
// kP: x fp32 -> g_xh half, pure streaming convert (16 floats / thread).
// ---------------------------------------------------------------------------
__global__ __launch_bounds__(256) void kP(const float* __restrict__ x) {
    size_t idx = ((size_t)blockIdx.x * 256 + threadIdx.x) * 16;
    float4 v[4];
#pragma unroll
    for (int q = 0; q < 4; q++) v[q] = *(const float4*)&x[idx + q * 4];
    uint32_t wv[8];
#pragma unroll
    for (int q = 0; q < 4; q++) {
        wv[2 * q]     = h2pack(v[q].x, v[q].y);
        wv[2 * q + 1] = h2pack(v[q].z, v[q].w);
    }
    __half* dst = g_xh + idx;
    *(uint4*)dst       = make_uint4(wv[0], wv[1], wv[2], wv[3]);
    *(uint4*)(dst + 8) = make_uint4(wv[4], wv[5], wv[6], wv[7]);
}

// ---------------------------------------------------------------------------
// k1: logits GEMM + BN + softmax + assignment^T(half) + a_sum.  (R12, unchanged)
// ---------------------------------------------------------------------------
#define K1_ST   15360
#define K1_CSO  10240
#define K1_SCF  46080
#define K1_SHF  46336
#define K1_RED  46592
#define K1_SMEM 48640

__device__ __forceinline__ void k1_issue(uint32_t sbase, const __half* xh,
                                         int c, int tid) {
    if (c < 16) {
        uint32_t st = sbase + (c % 3) * K1_ST;
        int d0 = c * 32;
#pragma unroll
        for (int p = 0; p < 2; p++) {
            int id = p * 256 + tid;
            int row = id >> 2, sq = id & 3;
            CP16(st + row * 80 + sq * 16, xh + (size_t)row * Dd + d0 + sq * 8);
        }
        {
            int row = tid >> 2, sq = tid & 3;
            CP16(st + K1_CSO + row * 80 + sq * 16,
                 g_ch + (size_t)row * Dd + d0 + sq * 8);
        }
    }
    CP_COMMIT();
}

__global__ __launch_bounds__(256) void k1_logits_softmax(
    const float* __restrict__ bnw,
    const float* __restrict__ bnb,
    const float* __restrict__ rm,
    const float* __restrict__ rv)
{
    extern __shared__ __align__(16) char sm[];
    float* scf = (float*)(sm + K1_SCF);
    float* shf = (float*)(sm + K1_SHF);
    float* red = (float*)(sm + K1_RED);
    const uint32_t sbase = smem_u32(sm);

    const int tid  = threadIdx.x;
    const int lane = tid & 31;
    const int w    = tid >> 5;
    const int la   = lane >> 2;
    const int lb   = lane & 3;
    const int row0 = blockIdx.x * 128;

    if (tid < 64) {
        float istd = rsqrtf(rv[tid] + 1e-5f);
        float s = bnw[tid] * istd;
        scf[tid] = s;
        shf[tid] = bnb[tid] - rm[tid] * s;
    }

    const __half* xh = g_xh + (size_t)row0 * Dd;

    float acc[8][4];
#pragma unroll
    for (int j = 0; j < 8; j++)
#pragma unroll
        for (int q = 0; q < 4; q++) acc[j][q] = 0.0f;

    k1_issue(sbase, xh, 0, tid);
    k1_issue(sbase, xh, 1, tid);

    const int wr = w * 16 + la;
    for (int c = 0; c < 16; c++) {
        __syncthreads();
        k1_issue(sbase, xh, c + 2, tid);
        CP_WAIT2();
        __syncthreads();

        const uint32_t* xsA = (const uint32_t*)(sm + (c % 3) * K1_ST);
        const uint32_t* csA = (const uint32_t*)(sm + (c % 3) * K1_ST + K1_CSO);
#pragma unroll
        for (int s = 0; s < 2; s++) {
            uint32_t a0 = xsA[wr * 20 + s * 8 + lb];
            uint32_t a1 = xsA[(wr + 8) * 20 + s * 8 + lb];
            uint32_t a2 = xsA[wr * 20 + s * 8 + 4 + lb];
            uint32_t a3 = xsA[(wr + 8) * 20 + s * 8 + 4 + lb];
#pragma unroll
            for (int j = 0; j < 8; j++) {
                uint32_t b0 = csA[(j * 8 + la) * 20 + s * 8 + lb];
                uint32_t b1 = csA[(j * 8 + la) * 20 + s * 8 + 4 + lb];
                mma16(acc[j], a0, a1, a2, a3, b0, b1);
            }
        }
    }
    __syncthreads();

    float vA[8][2], vB[8][2];
#pragma unroll
    for (int j = 0; j < 8; j++)
#pragma unroll
        for (int e = 0; e < 2; e++) {
            int col = j * 8 + lb * 2 + e;
            float s = scf[col], h = shf[col];
            vA[j][e] = acc[j][e]     * s + h;
            vB[j][e] = acc[j][2 + e] * s + h;
        }

    float mA = -1e30f, mB = -1e30f;
#pragma unroll
    for (int j = 0; j < 8; j++)
#pragma unroll
        for (int e = 0; e < 2; e++) { mA = fmaxf(mA, vA[j][e]); mB = fmaxf(mB, vB[j][e]); }
    mA = fmaxf(mA, __shfl_xor_sync(0xffffffffu, mA, 1));
    mA = fmaxf(mA, __shfl_xor_sync(0xffffffffu, mA, 2));
    mB = fmaxf(mB, __shfl_xor_sync(0xffffffffu, mB, 1));
    mB = fmaxf(mB, __shfl_xor_sync(0xffffffffu, mB, 2));
    float sA = 0.0f, sB = 0.0f;
#pragma unroll
    for (int j = 0; j < 8; j++)
#pragma unroll
        for (int e = 0; e < 2; e++) {
            vA[j][e] = __expf(vA[j][e] - mA); sA += vA[j][e];
            vB[j][e] = __expf(vB[j][e] - mB); sB += vB[j][e];
        }
    sA += __shfl_xor_sync(0xffffffffu, sA, 1);
    sA += __shfl_xor_sync(0xffffffffu, sA, 2);
    sB += __shfl_xor_sync(0xffffffffu, sB, 1);
    sB += __shfl_xor_sync(0xffffffffu, sB, 2);
    float invA = 1.0f / sA, invB = 1.0f / sB;

    float csum[8][2];
#pragma unroll
    for (int j = 0; j < 8; j++)
#pragma unroll
        for (int e = 0; e < 2; e++) {
            vA[j][e] *= invA;
            vB[j][e] *= invB;
            csum[j][e] = vA[j][e] + vB[j][e];
        }

#pragma unroll
    for (int j = 0; j < 8; j++)
#pragma unroll
        for (int e = 0; e < 2; e++) {
            csum[j][e] += __shfl_xor_sync(0xffffffffu, csum[j][e], 4);
            csum[j][e] += __shfl_xor_sync(0xffffffffu, csum[j][e], 8);
            csum[j][e] += __shfl_xor_sync(0xffffffffu, csum[j][e], 16);
        }
    if (la == 0) {
#pragma unroll
        for (int j = 0; j < 8; j++)
#pragma unroll
            for (int e = 0; e < 2; e++)
                red[w * 64 + j * 8 + lb * 2 + e] = csum[j][e];
    }
    __syncthreads();
    if (tid < 64) {
        float s = 0.0f;
#pragma unroll
        for (int q = 0; q < 8; q++) s += red[q * 64 + tid];
        atomicAdd(&g_asum[(row0 >> 12) * Kk + tid], s);
    }

    // write g_ah[b][k][n] via smem transpose (2 passes of 64 n)
    uint16_t* hb = (uint16_t*)sm;
    const int bb  = row0 >> 12;
    const int r0n = row0 & (Nn - 1);
#pragma unroll
    for (int p = 0; p < 2; p++) {
        __syncthreads();
        if ((w >> 2) == p) {
            int wl = w & 3;
            int lA = wl * 16 + la, lB = lA + 8;
#pragma unroll
            for (int j = 0; j < 8; j++) {
                *(uint32_t*)&hb[lA * 74 + j * 8 + lb * 2] = h2pack(vA[j][0], vA[j][1]);
                *(uint32_t*)&hb[lB * 74 + j * 8 + lb * 2] = h2pack(vB[j][0], vB[j][1]);
            }
        }
        __syncthreads();
        int k = tid >> 2, sg2 = tid & 3;
        uint32_t o[8];
#pragma unroll
        for (int q = 0; q < 8; q++) {
            uint32_t lo = hb[(sg2 * 16 + 2 * q)     * 74 + k];
            uint32_t hi = hb[(sg2 * 16 + 2 * q + 1) * 74 + k];
            o[q] = lo | (hi << 16);
        }
        __half* dst = g_ah + ((size_t)(bb * Kk + k)) * Nn + r0n + p * 64 + sg2 * 16;
        *(uint4*)dst       = make_uint4(o[0], o[1], o[2], o[3]);
        *(uint4*)(dst + 8) = make_uint4(o[4], o[5], o[6], o[7]);
    }
}

// ---------------------------------------------------------------------------
// k2: vlad partials. A = x tiles from g_xh[n][d] via ldmatrix.trans,
// B = g_ah rows [k][n]. 128 thr, tile 64d x 64k, n-chunk 32, 3-stage cp.async.
// smem x tile: [32 n][64 d halves], row stride 144B (conflict-free LDSM).
// ---------------------------------------------------------------------------
#define K2X_ST   4608              // 32 * 144
#define K2A_OFF  4608
#define K2_STAGE 9728              // x 4608 + ah 5120
#define K2_SMEM  29184

__device__ __forceinline__ void k2_issue(uint32_t sbase, const __half* xr,
                                         const __half* ar, int c, int tid) {
    if (c < Nn / NSPLIT / 32) {
        uint32_t st = sbase + (c % 3) * K2_STAGE;
        int n0 = c * 32;
#pragma unroll
        for (int p = 0; p < 2; p++) {
            int id = p * 128 + tid;
            // x: row = n (0..31), seg = 16B of d
            int xrow = id >> 3, xsg = id & 7;
            CP16(st + xrow * 144 + xsg * 16,
                 xr + (size_t)(n0 + xrow) * Dd + xsg * 8);
            // ah: row = k (0..63), seg = 16B of n
            int arow = id >> 2, asg = id & 3;
            CP16(st + K2A_OFF + arow * 80 + asg * 16,
                 ar + (size_t)arow * Nn + n0 + asg * 8);
        }
    }
    CP_COMMIT();
}

__global__ __launch_bounds__(128) void k2_vlad()
{
    extern __shared__ __align__(16) char sm[];
    const uint32_t sbase = smem_u32(sm);

    const int tid  = threadIdx.x;
    const int lane = tid & 31;
    const int w    = tid >> 5;
    const int la   = lane >> 2;
    const int lb   = lane & 3;
    const int b    = blockIdx.y;
    const int d0   = blockIdx.x * 64;
    const int s    = blockIdx.z;
    const int nbase = s * (Nn / NSPLIT);

    // xr: this block's 64-d window of xh rows
    const __half* xr = g_xh + ((size_t)(b * Nn + nbase)) * Dd + d0;
    const __half* ar = g_ah + ((size_t)(b * Kk)) * Nn + nbase;

    float acc[8][4];
#pragma unroll
    for (int j = 0; j < 8; j++)
#pragma unroll
        for (int q = 0; q < 4; q++) acc[j][q] = 0.0f;

    k2_issue(sbase, xr, ar, 0, tid);
    k2_issue(sbase, xr, ar, 1, tid);

    // LDSM address (bytes, within x tile): lane q=lane>>3, r=lane&7
    // matrix q: n_row = (q&2 ? 8:0)+r (+ss*16), d_col = w*16 + (q&1 ? 8:0)
    const int lq = lane >> 3, lr = lane & 7;
    const uint32_t xoff = ((lq >> 1) * 8 + lr) * 144 + (w * 16 + (lq & 1) * 8) * 2;

    const int L = Nn / NSPLIT / 32;
    for (int c = 0; c < L; c++) {
        __syncthreads();
        k2_issue(sbase, xr, ar, c + 2, tid);
        CP_WAIT2();
        __syncthreads();

        const uint32_t xbase = sbase + (c % 3) * K2_STAGE + xoff;
        const uint32_t* asA = (const uint32_t*)(sm + (c % 3) * K2_STAGE + K2A_OFF);
#pragma unroll
        for (int ss = 0; ss < 2; ss++) {
            uint32_t a0, a1, a2, a3;
            ldsm4t(a0, a1, a2, a3, xbase + ss * 16 * 144);
#pragma unroll
            for (int j = 0; j < 8; j++) {
                uint32_t b0 = asA[(j * 8 + la) * 20 + ss * 8 + lb];
                uint32_t b1 = asA[(j * 8 + la) * 20 + ss * 8 + 4 + lb];
                mma16(acc[j], a0, a1, a2, a3, b0, b1);
            }
        }
    }

    float* vp = g_vpart + ((size_t)s * Bb + b) * Kk * Dd;
    const int gdA = d0 + w * 16 + la;
    const int gdB = gdA + 8;
#pragma unroll
    for (int j = 0; j < 8; j++)
#pragma unroll
        for (int e = 0; e < 2; e++) {
            int col = j * 8 + lb * 2 + e;
            vp[(size_t)col * Dd + gdA] = acc[j][e];
            vp[(size_t)col * Dd + gdB] = acc[j][2 + e];
        }
}

// ---------------------------------------------------------------------------
__global__ __launch_bounds__(128) void k3_colnorm(const float* __restrict__ c2,
                                                  float* __restrict__ out)
{
    const int bk = blockIdx.x;
    const int b = bk >> 6;
    const int k = bk & 63;
    const int tid = threadIdx.x;
    const size_t SP = (size_t)Bb * Kk * Dd;

    const float a = g_asum[bk];
    const float* vr = g_vpart + (size_t)bk * Dd;

    float v[4];
    float ss = 0.0f;
#pragma unroll
    for (int p = 0; p < 4; p++) {
        int d = tid + p * 128;
        float t = vr[d] + vr[d + SP] - a * c2[(size_t)d * Kk + k];
        v[p] = t;
        ss += t * t;
    }
#pragma unroll
    for (int o = 16; o; o >>= 1) ss += __shfl_xor_sync(0xffffffffu, ss, o);

    __shared__ float sred[4];
    if ((tid & 31) == 0) sred[tid >> 5] = ss;
    __syncthreads();
    float tot = sred[0] + sred[1] + sred[2] + sred[3];
    float inv = 1.0f / fmaxf(sqrtf(tot), 1e-12f);
    if (tid == 0) atomicAdd(&g_gnormsq[b], tot * inv * inv);

    float* ob = out + (size_t)b * (Dd * Kk);
#pragma unroll
    for (int p = 0; p < 4; p++) {
        int d = tid + p * 128;
        ob[(size_t)d * Kk + k] = v[p] * inv;
    }
}

// ---------------------------------------------------------------------------
__global__ void k4_scale(float* __restrict__ out)
{
    int idx = blockIdx.x * 256 + threadIdx.x;
    int b = idx >> 15;
    out[idx] *= 1.0f / fmaxf(sqrtf(g_gnormsq[b]), 1e-12f);
}

// ---------------------------------------------------------------------------
extern "C" void kernel_launch(void* const* d_in, const int* in_sizes, int n_in,
                              void* d_out, int out_size)
{
    const float* x        = (const float*)d_in[0];
    const float* clusters = (const float*)d_in[1];
    const float* c2       = (const float*)d_in[2];
    const float* bnw      = (const float*)d_in[3];
    const float* bnb      = (const float*)d_in[4];
    const float* rm       = (const float*)d_in[5];
    const float* rv       = (const float*)d_in[6];
    float* out = (float*)d_out;

    k0_init<<<8, 256>>>();
    kC<<<32, 256>>>(clusters);
    kP<<<(int)(((size_t)Bb * Nn * Dd) / 16 / 256), 256>>>(x);
    k1_logits_softmax<<<(Bb * Nn) / 128, 256, K1_SMEM>>>(bnw, bnb, rm, rv);
    dim3 g2(Dd / 64, Bb, NSPLIT);
    k2_vlad<<<g2, 128, K2_SMEM>>>();
    k3_colnorm<<<Bb * Kk, 128>>>(c2, out);
    k4_scale<<<(Bb * Dd * Kk) / 256, 256>>>(out);
}

// round 14
// speedup vs baseline: 2.0097x; 1.0577x over previous
#include <cuda_runtime.h>
#include <cuda_fp16.h>
#include <math.h>
#include <stdint.h>

// B=32, N=4096, D=512, K=64
#define Bb 32
#define Nn 4096
#define Dd 512
#define Kk 64
#define NSPLIT 2

__device__ __half g_xh[(size_t)Bb * Nn * Dd];              // x as half, [n][d] (written by k1)
__device__ __half g_ch[(size_t)Kk * Dd];                   // clusters^T half [k][d]
__device__ __half g_ah[(size_t)Bb * Kk * Nn];              // assignment^T half [b][k][n]
__device__ float  g_vpart[(size_t)NSPLIT * Bb * Kk * Dd];  // vlad partials [s,b,k,d]
__device__ float  g_asum[Bb * Kk];
__device__ float  g_gnormsq[Bb];

__device__ __forceinline__ uint32_t h2pack(float lo, float hi) {
    __half2 h = __floats2half2_rn(lo, hi);
    return *(uint32_t*)&h;
}

__device__ __forceinline__ void mma16(float* c, uint32_t a0, uint32_t a1,
                                      uint32_t a2, uint32_t a3,
                                      uint32_t b0, uint32_t b1) {
    asm volatile(
        "mma.sync.aligned.m16n8k16.row.col.f32.f16.f16.f32 "
        "{%0,%1,%2,%3},{%4,%5,%6,%7},{%8,%9},{%0,%1,%2,%3};\n"
        : "+f"(c[0]), "+f"(c[1]), "+f"(c[2]), "+f"(c[3])
        : "r"(a0), "r"(a1), "r"(a2), "r"(a3), "r"(b0), "r"(b1));
}

__device__ __forceinline__ void ldsm4t(uint32_t& r0, uint32_t& r1,
                                       uint32_t& r2, uint32_t& r3, uint32_t a) {
    asm volatile(
        "ldmatrix.sync.aligned.m8n8.x4.trans.shared.b16 {%0,%1,%2,%3}, [%4];"
        : "=r"(r0), "=r"(r1), "=r"(r2), "=r"(r3) : "r"(a));
}

__device__ __forceinline__ uint32_t smem_u32(const void* p) {
    uint32_t a;
    asm("{ .reg .u64 t; cvta.to.shared.u64 t, %1; cvt.u32.u64 %0, t; }"
        : "=r"(a) : "l"(p));
    return a;
}

#define CP16(dst, src) \
    asm volatile("cp.async.cg.shared.global [%0], [%1], 16;\n" \
                 :: "r"(dst), "l"(src) : "memory")
#define CP_COMMIT() asm volatile("cp.async.commit_group;\n" ::: "memory")
#define CP_WAIT1()  asm volatile("cp.async.wait_group 1;\n" ::: "memory")
#define CP_WAIT2()  asm volatile("cp.async.wait_group 2;\n" ::: "memory")

// ---------------------------------------------------------------------------
__global__ void k0_init() {
    int i = blockIdx.x * 256 + threadIdx.x;
    if (i < Bb * Kk) g_asum[i] = 0.0f;
    if (i < Bb)      g_gnormsq[i] = 0.0f;
}

// ---------------------------------------------------------------------------
// kC: clusters [d][k] fp32 -> g_ch [k][d] half
// ---------------------------------------------------------------------------
__global__ __launch_bounds__(256) void kC(const float* __restrict__ clusters) {
    int idx4 = (blockIdx.x * 256 + threadIdx.x) * 4;   // 32 blocks cover 32768
    int d = idx4 >> 6, k = idx4 & 63;
    float4 c = *(const float4*)&clusters[idx4];
    g_ch[(size_t)(k + 0) * Dd + d] = __float2half_rn(c.x);
    g_ch[(size_t)(k + 1) * Dd + d] = __float2half_rn(c.y);
    g_ch[(size_t)(k + 2) * Dd + d] = __float2half_rn(c.z);
    g_ch[(size_t)(k + 3) * Dd + d] = __float2half_rn(c.w);
}

// ---------------------------------------------------------------------------
// k1: reads x fp32 directly (2-stage cp.async), converts to half in smem
// (also streaming the half tile out to g_xh for k2), fp16 MMA + BN + softmax
// + assignment^T(half) + a_sum.  256 thr, tile 128n x 64k, K chunk 32.
// smem map:
//   stage s (s=0,1) at s*23552:  xF fp32 [128][144B] (18432) + cs half [64][80B] (5120)
//   xsH half tile  @ 47104: [128][80B] = 10240   (fragment layout, as R13)
//   scf @ 57344, shf @ 57600, red @ 57856 (+2048)  => total 59904
// ---------------------------------------------------------------------------
#define K1F_CS   18432
#define K1F_ST   23552
#define K1_XSH   47104
#define K1_SCF   57344
#define K1_SHF   57600
#define K1_RED   57856
#define K1_SMEM  59904

__device__ __forceinline__ void k1_issue(uint32_t sbase, const float* xg,
                                         int c, int tid) {
    if (c < 16) {
        uint32_t st = sbase + (c & 1) * K1F_ST;
        int d0 = c * 32;
        // x fp32: 128 rows x 128B  (1024 x 16B ops / 256 thr = 4 each)
#pragma unroll
        for (int p = 0; p < 4; p++) {
            int id = p * 256 + tid;
            int row = id >> 3, sq = id & 7;
            CP16(st + row * 144 + sq * 16,
                 xg + (size_t)row * Dd + d0 + sq * 4);
        }
        // clusters^T half: 64 rows x 64B
        {
            int row = tid >> 2, sq = tid & 3;
            CP16(st + K1F_CS + row * 80 + sq * 16,
                 g_ch + (size_t)row * Dd + d0 + sq * 8);
        }
    }
    CP_COMMIT();
}

__global__ __launch_bounds__(256) void k1_logits_softmax(
    const float* __restrict__ x,
    const float* __restrict__ bnw,
    const float* __restrict__ bnb,
    const float* __restrict__ rm,
    const float* __restrict__ rv)
{
    extern __shared__ __align__(16) char sm[];
    float* scf = (float*)(sm + K1_SCF);
    float* shf = (float*)(sm + K1_SHF);
    float* red = (float*)(sm + K1_RED);
    uint32_t* xh32 = (uint32_t*)(sm + K1_XSH);
    const uint32_t sbase = smem_u32(sm);

    const int tid  = threadIdx.x;
    const int lane = tid & 31;
    const int w    = tid >> 5;
    const int la   = lane >> 2;
    const int lb   = lane & 3;
    const int row0 = blockIdx.x * 128;

    if (tid < 64) {
        float istd = rsqrtf(rv[tid] + 1e-5f);
        float s = bnw[tid] * istd;
        scf[tid] = s;
        shf[tid] = bnb[tid] - rm[tid] * s;
    }

    const float* xg = x + (size_t)row0 * Dd;

    float acc[8][4];
#pragma unroll
    for (int j = 0; j < 8; j++)
#pragma unroll
        for (int q = 0; q < 4; q++) acc[j][q] = 0.0f;

    k1_issue(sbase, xg, 0, tid);

    const int wr = w * 16 + la;
    const int crow = tid >> 1;           // convert: row 0..127
    const int ch   = tid & 1;            // convert: half-of-row (16 floats)

    for (int c = 0; c < 16; c++) {
        __syncthreads();                 // stage (c+1)&1 free (prev readers done)
        k1_issue(sbase, xg, c + 1, tid);
        CP_WAIT1();                      // group c complete
        __syncthreads();

        // ---- convert chunk c: fp32 stage -> xsH half tile + g_xh global ----
        {
            const char* stx = sm + (c & 1) * K1F_ST;
            const float4* src = (const float4*)(stx + crow * 144 + ch * 64);
            float4 v0 = src[0], v1 = src[1], v2 = src[2], v3 = src[3];
            uint32_t wv[8];
            wv[0] = h2pack(v0.x, v0.y); wv[1] = h2pack(v0.z, v0.w);
            wv[2] = h2pack(v1.x, v1.y); wv[3] = h2pack(v1.z, v1.w);
            wv[4] = h2pack(v2.x, v2.y); wv[5] = h2pack(v2.z, v2.w);
            wv[6] = h2pack(v3.x, v3.y); wv[7] = h2pack(v3.z, v3.w);
            *(uint4*)&xh32[crow * 20 + ch * 8]     = make_uint4(wv[0], wv[1], wv[2], wv[3]);
            *(uint4*)&xh32[crow * 20 + ch * 8 + 4] = make_uint4(wv[4], wv[5], wv[6], wv[7]);
            __half* gd = g_xh + (size_t)(row0 + crow) * Dd + c * 32 + ch * 16;
            *(uint4*)gd       = make_uint4(wv[0], wv[1], wv[2], wv[3]);
            *(uint4*)(gd + 8) = make_uint4(wv[4], wv[5], wv[6], wv[7]);
        }
        __syncthreads();

        // ---- MMA on chunk c ----
        const uint32_t* csA = (const uint32_t*)(sm + (c & 1) * K1F_ST + K1F_CS);
#pragma unroll
        for (int s = 0; s < 2; s++) {
            uint32_t a0 = xh32[wr * 20 + s * 8 + lb];
            uint32_t a1 = xh32[(wr + 8) * 20 + s * 8 + lb];
            uint32_t a2 = xh32[wr * 20 + s * 8 + 4 + lb];
            uint32_t a3 = xh32[(wr + 8) * 20 + s * 8 + 4 + lb];
#pragma unroll
            for (int j = 0; j < 8; j++) {
                uint32_t b0 = csA[(j * 8 + la) * 20 + s * 8 + lb];
                uint32_t b1 = csA[(j * 8 + la) * 20 + s * 8 + 4 + lb];
                mma16(acc[j], a0, a1, a2, a3, b0, b1);
            }
        }
    }
    __syncthreads();

    // ---- BN + softmax (identical numerics) ----
    float vA[8][2], vB[8][2];
#pragma unroll
    for (int j = 0; j < 8; j++)
#pragma unroll
        for (int e = 0; e < 2; e++) {
            int col = j * 8 + lb * 2 + e;
            float s = scf[col], h = shf[col];
            vA[j][e] = acc[j][e]     * s + h;
            vB[j][e] = acc[j][2 + e] * s + h;
        }

    float mA = -1e30f, mB = -1e30f;
#pragma unroll
    for (int j = 0; j < 8; j++)
#pragma unroll
        for (int e = 0; e < 2; e++) { mA = fmaxf(mA, vA[j][e]); mB = fmaxf(mB, vB[j][e]); }
    mA = fmaxf(mA, __shfl_xor_sync(0xffffffffu, mA, 1));
    mA = fmaxf(mA, __shfl_xor_sync(0xffffffffu, mA, 2));
    mB = fmaxf(mB, __shfl_xor_sync(0xffffffffu, mB, 1));
    mB = fmaxf(mB, __shfl_xor_sync(0xffffffffu, mB, 2));
    float sA = 0.0f, sB = 0.0f;
#pragma unroll
    for (int j = 0; j < 8; j++)
#pragma unroll
        for (int e = 0; e < 2; e++) {
            vA[j][e] = __expf(vA[j][e] - mA); sA += vA[j][e];
            vB[j][e] = __expf(vB[j][e] - mB); sB += vB[j][e];
        }
    sA += __shfl_xor_sync(0xffffffffu, sA, 1);
    sA += __shfl_xor_sync(0xffffffffu, sA, 2);
    sB += __shfl_xor_sync(0xffffffffu, sB, 1);
    sB += __shfl_xor_sync(0xffffffffu, sB, 2);
    float invA = 1.0f / sA, invB = 1.0f / sB;

    float csum[8][2];
#pragma unroll
    for (int j = 0; j < 8; j++)
#pragma unroll
        for (int e = 0; e < 2; e++) {
            vA[j][e] *= invA;
            vB[j][e] *= invB;
            csum[j][e] = vA[j][e] + vB[j][e];
        }

#pragma unroll
    for (int j = 0; j < 8; j++)
#pragma unroll
        for (int e = 0; e < 2; e++) {
            csum[j][e] += __shfl_xor_sync(0xffffffffu, csum[j][e], 4);
            csum[j][e] += __shfl_xor_sync(0xffffffffu, csum[j][e], 8);
            csum[j][e] += __shfl_xor_sync(0xffffffffu, csum[j][e], 16);
        }
    if (la == 0) {
#pragma unroll
        for (int j = 0; j < 8; j++)
#pragma unroll
            for (int e = 0; e < 2; e++)
                red[w * 64 + j * 8 + lb * 2 + e] = csum[j][e];
    }
    __syncthreads();
    if (tid < 64) {
        float s = 0.0f;
#pragma unroll
        for (int q = 0; q < 8; q++) s += red[q * 64 + tid];
        atomicAdd(&g_asum[(row0 >> 12) * Kk + tid], s);
    }

    // ---- write g_ah[b][k][n] via smem transpose (2 passes of 64 n) ----
    uint16_t* hb = (uint16_t*)sm;
    const int bb  = row0 >> 12;
    const int r0n = row0 & (Nn - 1);
#pragma unroll
    for (int p = 0; p < 2; p++) {
        __syncthreads();
        if ((w >> 2) == p) {
            int wl = w & 3;
            int lA = wl * 16 + la, lB = lA + 8;
#pragma unroll
            for (int j = 0; j < 8; j++) {
                *(uint32_t*)&hb[lA * 74 + j * 8 + lb * 2] = h2pack(vA[j][0], vA[j][1]);
                *(uint32_t*)&hb[lB * 74 + j * 8 + lb * 2] = h2pack(vB[j][0], vB[j][1]);
            }
        }
        __syncthreads();
        int k = tid >> 2, sg2 = tid & 3;
        uint32_t o[8];
#pragma unroll
        for (int q = 0; q < 8; q++) {
            uint32_t lo = hb[(sg2 * 16 + 2 * q)     * 74 + k];
            uint32_t hi = hb[(sg2 * 16 + 2 * q + 1) * 74 + k];
            o[q] = lo | (hi << 16);
        }
        __half* dst = g_ah + ((size_t)(bb * Kk + k)) * Nn + r0n + p * 64 + sg2 * 16;
        *(uint4*)dst       = make_uint4(o[0], o[1], o[2], o[3]);
        *(uint4*)(dst + 8) = make_uint4(o[4], o[5], o[6], o[7]);
    }
}

// ---------------------------------------------------------------------------
// k2: vlad partials (unchanged from R13). A = g_xh tiles via ldmatrix.trans,
// B = g_ah rows. 128 thr, tile 64d x 64k, n-chunk 32, 3-stage cp.async.
// ---------------------------------------------------------------------------
#define K2A_OFF  4608
#define K2_STAGE 9728
#define K2_SMEM  29184

__device__ __forceinline__ void k2_issue(uint32_t sbase, const __half* xr,
                                         const __half* ar, int c, int tid) {
    if (c < Nn / NSPLIT / 32) {
        uint32_t st = sbase + (c % 3) * K2_STAGE;
        int n0 = c * 32;
#pragma unroll
        for (int p = 0; p < 2; p++) {
            int id = p * 128 + tid;
            int xrow = id >> 3, xsg = id & 7;
            CP16(st + xrow * 144 + xsg * 16,
                 xr + (size_t)(n0 + xrow) * Dd + xsg * 8);
            int arow = id >> 2, asg = id & 3;
            CP16(st + K2A_OFF + arow * 80 + asg * 16,
                 ar + (size_t)arow * Nn + n0 + asg * 8);
        }
    }
    CP_COMMIT();
}

__global__ __launch_bounds__(128) void k2_vlad()
{
    extern __shared__ __align__(16) char sm[];
    const uint32_t sbase = smem_u32(sm);

    const int tid  = threadIdx.x;
    const int lane = tid & 31;
    const int w    = tid >> 5;
    const int la   = lane >> 2;
    const int lb   = lane & 3;
    const int b    = blockIdx.y;
    const int d0   = blockIdx.x * 64;
    const int s    = blockIdx.z;
    const int nbase = s * (Nn / NSPLIT);

    const __half* xr = g_xh + ((size_t)(b * Nn + nbase)) * Dd + d0;
    const __half* ar = g_ah + ((size_t)(b * Kk)) * Nn + nbase;

    float acc[8][4];
#pragma unroll
    for (int j = 0; j < 8; j++)
#pragma unroll
        for (int q = 0; q < 4; q++) acc[j][q] = 0.0f;

    k2_issue(sbase, xr, ar, 0, tid);
    k2_issue(sbase, xr, ar, 1, tid);

    const int lq = lane >> 3, lr = lane & 7;
    const uint32_t xoff = ((lq >> 1) * 8 + lr) * 144 + (w * 16 + (lq & 1) * 8) * 2;

    const int L = Nn / NSPLIT / 32;
    for (int c = 0; c < L; c++) {
        __syncthreads();
        k2_issue(sbase, xr, ar, c + 2, tid);
        CP_WAIT2();
        __syncthreads();

        const uint32_t xbase = sbase + (c % 3) * K2_STAGE + xoff;
        const uint32_t* asA = (const uint32_t*)(sm + (c % 3) * K2_STAGE + K2A_OFF);
#pragma unroll
        for (int ss = 0; ss < 2; ss++) {
            uint32_t a0, a1, a2, a3;
            ldsm4t(a0, a1, a2, a3, xbase + ss * 16 * 144);
#pragma unroll
            for (int j = 0; j < 8; j++) {
                uint32_t b0 = asA[(j * 8 + la) * 20 + ss * 8 + lb];
                uint32_t b1 = asA[(j * 8 + la) * 20 + ss * 8 + 4 + lb];
                mma16(acc[j], a0, a1, a2, a3, b0, b1);
            }
        }
    }

    float* vp = g_vpart + ((size_t)s * Bb + b) * Kk * Dd;
    const int gdA = d0 + w * 16 + la;
    const int gdB = gdA + 8;
#pragma unroll
    for (int j = 0; j < 8; j++)
#pragma unroll
        for (int e = 0; e < 2; e++) {
            int col = j * 8 + lb * 2 + e;
            vp[(size_t)col * Dd + gdA] = acc[j][e];
            vp[(size_t)col * Dd + gdB] = acc[j][2 + e];
        }
}

// ---------------------------------------------------------------------------
__global__ __launch_bounds__(128) void k3_colnorm(const float* __restrict__ c2,
                                                  float* __restrict__ out)
{
    const int bk = blockIdx.x;
    const int b = bk >> 6;
    const int k = bk & 63;
    const int tid = threadIdx.x;
    const size_t SP = (size_t)Bb * Kk * Dd;

    const float a = g_asum[bk];
    const float* vr = g_vpart + (size_t)bk * Dd;

    float v[4];
    float ss = 0.0f;
#pragma unroll
    for (int p = 0; p < 4; p++) {
        int d = tid + p * 128;
        float t = vr[d] + vr[d + SP] - a * c2[(size_t)d * Kk + k];
        v[p] = t;
        ss += t * t;
    }
#pragma unroll
    for (int o = 16; o; o >>= 1) ss += __shfl_xor_sync(0xffffffffu, ss, o);

    __shared__ float sred[4];
    if ((tid & 31) == 0) sred[tid >> 5] = ss;
    __syncthreads();
    float tot = sred[0] + sred[1] + sred[2] + sred[3];
    float inv = 1.0f / fmaxf(sqrtf(tot), 1e-12f);
    if (tid == 0) atomicAdd(&g_gnormsq[b], tot * inv * inv);

    float* ob = out + (size_t)b * (Dd * Kk);
#pragma unroll
    for (int p = 0; p < 4; p++) {
        int d = tid + p * 128;
        ob[(size_t)d * Kk + k] = v[p] * inv;
    }
}

// ---------------------------------------------------------------------------
__global__ void k4_scale(float* __restrict__ out)
{
    int idx = blockIdx.x * 256 + threadIdx.x;
    int b = idx >> 15;
    out[idx] *= 1.0f / fmaxf(sqrtf(g_gnormsq[b]), 1e-12f);
}

// ---------------------------------------------------------------------------
extern "C" void kernel_launch(void* const* d_in, const int* in_sizes, int n_in,
                              void* d_out, int out_size)
{
    const float* x        = (const float*)d_in[0];
    const float* clusters = (const float*)d_in[1];
    const float* c2       = (const float*)d_in[2];
    const float* bnw      = (const float*)d_in[3];
    const float* bnb      = (const float*)d_in[4];
    const float* rm       = (const float*)d_in[5];
    const float* rv       = (const float*)d_in[6];
    float* out = (float*)d_out;

    cudaFuncSetAttribute(k1_logits_softmax,
                         cudaFuncAttributeMaxDynamicSharedMemorySize, K1_SMEM);

    k0_init<<<8, 256>>>();
    kC<<<32, 256>>>(clusters);
    k1_logits_softmax<<<(Bb * Nn) / 128, 256, K1_SMEM>>>(x, bnw, bnb, rm, rv);
    dim3 g2(Dd / 64, Bb, NSPLIT);
    k2_vlad<<<g2, 128, K2_SMEM>>>();
    k3_colnorm<<<Bb * Kk, 128>>>(c2, out);
    k4_scale<<<(Bb * Dd * Kk) / 256, 256>>>(out);
}

// round 15
// speedup vs baseline: 2.0685x; 1.0293x over previous
#include <cuda_runtime.h>
#include <cuda_fp16.h>
#include <math.h>
#include <stdint.h>

// B=32, N=4096, D=512, K=64
#define Bb 32
#define Nn 4096
#define Dd 512
#define Kk 64
#define NSPLIT 4

__device__ __half g_xh[(size_t)Bb * Nn * Dd];              // x as half, [n][d] (written by k1)
__device__ __half g_ch[(size_t)Kk * Dd];                   // clusters^T half [k][d]
__device__ __half g_ah[(size_t)Bb * Kk * Nn];              // assignment^T half [b][k][n]
__device__ float  g_vpart[(size_t)NSPLIT * Bb * Kk * Dd];  // vlad partials [s,b,k,d]
__device__ float  g_asum[Bb * Kk];
__device__ float  g_gnormsq[Bb];

__device__ __forceinline__ uint32_t h2pack(float lo, float hi) {
    __half2 h = __floats2half2_rn(lo, hi);
    return *(uint32_t*)&h;
}

__device__ __forceinline__ void mma16(float* c, uint32_t a0, uint32_t a1,
                                      uint32_t a2, uint32_t a3,
                                      uint32_t b0, uint32_t b1) {
    asm volatile(
        "mma.sync.aligned.m16n8k16.row.col.f32.f16.f16.f32 "
        "{%0,%1,%2,%3},{%4,%5,%6,%7},{%8,%9},{%0,%1,%2,%3};\n"
        : "+f"(c[0]), "+f"(c[1]), "+f"(c[2]), "+f"(c[3])
        : "r"(a0), "r"(a1), "r"(a2), "r"(a3), "r"(b0), "r"(b1));
}

__device__ __forceinline__ void ldsm4t(uint32_t& r0, uint32_t& r1,
                                       uint32_t& r2, uint32_t& r3, uint32_t a) {
    asm volatile(
        "ldmatrix.sync.aligned.m8n8.x4.trans.shared.b16 {%0,%1,%2,%3}, [%4];"
        : "=r"(r0), "=r"(r1), "=r"(r2), "=r"(r3) : "r"(a));
}

__device__ __forceinline__ uint32_t smem_u32(const void* p) {
    uint32_t a;
    asm("{ .reg .u64 t; cvta.to.shared.u64 t, %1; cvt.u32.u64 %0, t; }"
        : "=r"(a) : "l"(p));
    return a;
}

#define CP16(dst, src) \
    asm volatile("cp.async.cg.shared.global [%0], [%1], 16;\n" \
                 :: "r"(dst), "l"(src) : "memory")
#define CP_COMMIT() asm volatile("cp.async.commit_group;\n" ::: "memory")
#define CP_WAIT1()  asm volatile("cp.async.wait_group 1;\n" ::: "memory")
#define CP_WAIT2()  asm volatile("cp.async.wait_group 2;\n" ::: "memory")

// ---------------------------------------------------------------------------
__global__ void k0_init() {
    int i = blockIdx.x * 256 + threadIdx.x;
    if (i < Bb * Kk) g_asum[i] = 0.0f;
    if (i < Bb)      g_gnormsq[i] = 0.0f;
}

// ---------------------------------------------------------------------------
// kC: clusters [d][k] fp32 -> g_ch [k][d] half
// ---------------------------------------------------------------------------
__global__ __launch_bounds__(256) void kC(const float* __restrict__ clusters) {
    int idx4 = (blockIdx.x * 256 + threadIdx.x) * 4;   // 32 blocks cover 32768
    int d = idx4 >> 6, k = idx4 & 63;
    float4 c = *(const float4*)&clusters[idx4];
    g_ch[(size_t)(k + 0) * Dd + d] = __float2half_rn(c.x);
    g_ch[(size_t)(k + 1) * Dd + d] = __float2half_rn(c.y);
    g_ch[(size_t)(k + 2) * Dd + d] = __float2half_rn(c.z);
    g_ch[(size_t)(k + 3) * Dd + d] = __float2half_rn(c.w);
}

// ---------------------------------------------------------------------------
// k1: reads x fp32 directly (2-stage cp.async), converts to half in smem
// (also streaming the half tile out to g_xh for k2), fp16 MMA + BN + softmax
// + assignment^T(half) + a_sum.  256 thr, tile 128n x 64k, K chunk 32.
// ---------------------------------------------------------------------------
#define K1F_CS   18432
#define K1F_ST   23552
#define K1_XSH   47104
#define K1_SCF   57344
#define K1_SHF   57600
#define K1_RED   57856
#define K1_SMEM  59904

__device__ __forceinline__ void k1_issue(uint32_t sbase, const float* xg,
                                         int c, int tid) {
    if (c < 16) {
        uint32_t st = sbase + (c & 1) * K1F_ST;
        int d0 = c * 32;
#pragma unroll
        for (int p = 0; p < 4; p++) {
            int id = p * 256 + tid;
            int row = id >> 3, sq = id & 7;
            CP16(st + row * 144 + sq * 16,
                 xg + (size_t)row * Dd + d0 + sq * 4);
        }
        {
            int row = tid >> 2, sq = tid & 3;
            CP16(st + K1F_CS + row * 80 + sq * 16,
                 g_ch + (size_t)row * Dd + d0 + sq * 8);
        }
    }
    CP_COMMIT();
}

__global__ __launch_bounds__(256) void k1_logits_softmax(
    const float* __restrict__ x,
    const float* __restrict__ bnw,
    const float* __restrict__ bnb,
    const float* __restrict__ rm,
    const float* __restrict__ rv)
{
    extern __shared__ __align__(16) char sm[];
    float* scf = (float*)(sm + K1_SCF);
    float* shf = (float*)(sm + K1_SHF);
    float* red = (float*)(sm + K1_RED);
    uint32_t* xh32 = (uint32_t*)(sm + K1_XSH);
    const uint32_t sbase = smem_u32(sm);

    const int tid  = threadIdx.x;
    const int lane = tid & 31;
    const int w    = tid >> 5;
    const int la   = lane >> 2;
    const int lb   = lane & 3;
    const int row0 = blockIdx.x * 128;

    if (tid < 64) {
        float istd = rsqrtf(rv[tid] + 1e-5f);
        float s = bnw[tid] * istd;
        scf[tid] = s;
        shf[tid] = bnb[tid] - rm[tid] * s;
    }

    const float* xg = x + (size_t)row0 * Dd;

    float acc[8][4];
#pragma unroll
    for (int j = 0; j < 8; j++)
#pragma unroll
        for (int q = 0; q < 4; q++) acc[j][q] = 0.0f;

    k1_issue(sbase, xg, 0, tid);

    const int wr = w * 16 + la;
    const int crow = tid >> 1;
    const int ch   = tid & 1;

    for (int c = 0; c < 16; c++) {
        __syncthreads();
        k1_issue(sbase, xg, c + 1, tid);
        CP_WAIT1();
        __syncthreads();

        // convert chunk c: fp32 stage -> xsH half tile + g_xh global
        {
            const char* stx = sm + (c & 1) * K1F_ST;
            const float4* src = (const float4*)(stx + crow * 144 + ch * 64);
            float4 v0 = src[0], v1 = src[1], v2 = src[2], v3 = src[3];
            uint32_t wv[8];
            wv[0] = h2pack(v0.x, v0.y); wv[1] = h2pack(v0.z, v0.w);
            wv[2] = h2pack(v1.x, v1.y); wv[3] = h2pack(v1.z, v1.w);
            wv[4] = h2pack(v2.x, v2.y); wv[5] = h2pack(v2.z, v2.w);
            wv[6] = h2pack(v3.x, v3.y); wv[7] = h2pack(v3.z, v3.w);
            *(uint4*)&xh32[crow * 20 + ch * 8]     = make_uint4(wv[0], wv[1], wv[2], wv[3]);
            *(uint4*)&xh32[crow * 20 + ch * 8 + 4] = make_uint4(wv[4], wv[5], wv[6], wv[7]);
            __half* gd = g_xh + (size_t)(row0 + crow) * Dd + c * 32 + ch * 16;
            *(uint4*)gd       = make_uint4(wv[0], wv[1], wv[2], wv[3]);
            *(uint4*)(gd + 8) = make_uint4(wv[4], wv[5], wv[6], wv[7]);
        }
        __syncthreads();

        const uint32_t* csA = (const uint32_t*)(sm + (c & 1) * K1F_ST + K1F_CS);
#pragma unroll
        for (int s = 0; s < 2; s++) {
            uint32_t a0 = xh32[wr * 20 + s * 8 + lb];
            uint32_t a1 = xh32[(wr + 8) * 20 + s * 8 + lb];
            uint32_t a2 = xh32[wr * 20 + s * 8 + 4 + lb];
            uint32_t a3 = xh32[(wr + 8) * 20 + s * 8 + 4 + lb];
#pragma unroll
            for (int j = 0; j < 8; j++) {
                uint32_t b0 = csA[(j * 8 + la) * 20 + s * 8 + lb];
                uint32_t b1 = csA[(j * 8 + la) * 20 + s * 8 + 4 + lb];
                mma16(acc[j], a0, a1, a2, a3, b0, b1);
            }
        }
    }
    __syncthreads();

    float vA[8][2], vB[8][2];
#pragma unroll
    for (int j = 0; j < 8; j++)
#pragma unroll
        for (int e = 0; e < 2; e++) {
            int col = j * 8 + lb * 2 + e;
            float s = scf[col], h = shf[col];
            vA[j][e] = acc[j][e]     * s + h;
            vB[j][e] = acc[j][2 + e] * s + h;
        }

    float mA = -1e30f, mB = -1e30f;
#pragma unroll
    for (int j = 0; j < 8; j++)
#pragma unroll
        for (int e = 0; e < 2; e++) { mA = fmaxf(mA, vA[j][e]); mB = fmaxf(mB, vB[j][e]); }
    mA = fmaxf(mA, __shfl_xor_sync(0xffffffffu, mA, 1));
    mA = fmaxf(mA, __shfl_xor_sync(0xffffffffu, mA, 2));
    mB = fmaxf(mB, __shfl_xor_sync(0xffffffffu, mB, 1));
    mB = fmaxf(mB, __shfl_xor_sync(0xffffffffu, mB, 2));
    float sA = 0.0f, sB = 0.0f;
#pragma unroll
    for (int j = 0; j < 8; j++)
#pragma unroll
        for (int e = 0; e < 2; e++) {
            vA[j][e] = __expf(vA[j][e] - mA); sA += vA[j][e];
            vB[j][e] = __expf(vB[j][e] - mB); sB += vB[j][e];
        }
    sA += __shfl_xor_sync(0xffffffffu, sA, 1);
    sA += __shfl_xor_sync(0xffffffffu, sA, 2);
    sB += __shfl_xor_sync(0xffffffffu, sB, 1);
    sB += __shfl_xor_sync(0xffffffffu, sB, 2);
    float invA = 1.0f / sA, invB = 1.0f / sB;

    float csum[8][2];
#pragma unroll
    for (int j = 0; j < 8; j++)
#pragma unroll
        for (int e = 0; e < 2; e++) {
            vA[j][e] *= invA;
            vB[j][e] *= invB;
            csum[j][e] = vA[j][e] + vB[j][e];
        }

#pragma unroll
    for (int j = 0; j < 8; j++)
#pragma unroll
        for (int e = 0; e < 2; e++) {
            csum[j][e] += __shfl_xor_sync(0xffffffffu, csum[j][e], 4);
            csum[j][e] += __shfl_xor_sync(0xffffffffu, csum[j][e], 8);
            csum[j][e] += __shfl_xor_sync(0xffffffffu, csum[j][e], 16);
        }
    if (la == 0) {
#pragma unroll
        for (int j = 0; j < 8; j++)
#pragma unroll
            for (int e = 0; e < 2; e++)
                red[w * 64 + j * 8 + lb * 2 + e] = csum[j][e];
    }
    __syncthreads();
    if (tid < 64) {
        float s = 0.0f;
#pragma unroll
        for (int q = 0; q < 8; q++) s += red[q * 64 + tid];
        atomicAdd(&g_asum[(row0 >> 12) * Kk + tid], s);
    }

    // write g_ah[b][k][n] via smem transpose (2 passes of 64 n)
    uint16_t* hb = (uint16_t*)sm;
    const int bb  = row0 >> 12;
    const int r0n = row0 & (Nn - 1);
#pragma unroll
    for (int p = 0; p < 2; p++) {
        __syncthreads();
        if ((w >> 2) == p) {
            int wl = w & 3;
            int lA = wl * 16 + la, lB = lA + 8;
#pragma unroll
            for (int j = 0; j < 8; j++) {
                *(uint32_t*)&hb[lA * 74 + j * 8 + lb * 2] = h2pack(vA[j][0], vA[j][1]);
                *(uint32_t*)&hb[lB * 74 + j * 8 + lb * 2] = h2pack(vB[j][0], vB[j][1]);
            }
        }
        __syncthreads();
        int k = tid >> 2, sg2 = tid & 3;
        uint32_t o[8];
#pragma unroll
        for (int q = 0; q < 8; q++) {
            uint32_t lo = hb[(sg2 * 16 + 2 * q)     * 74 + k];
            uint32_t hi = hb[(sg2 * 16 + 2 * q + 1) * 74 + k];
            o[q] = lo | (hi << 16);
        }
        __half* dst = g_ah + ((size_t)(bb * Kk + k)) * Nn + r0n + p * 64 + sg2 * 16;
        *(uint4*)dst       = make_uint4(o[0], o[1], o[2], o[3]);
        *(uint4*)(dst + 8) = make_uint4(o[4], o[5], o[6], o[7]);
    }
}

// ---------------------------------------------------------------------------
// k2: vlad partials. A = g_xh tiles via ldmatrix.trans, B = g_ah rows.
// 128 thr, tile 64d x 64k, n-chunk 32, 3-stage cp.async.
// NSPLIT=4 -> grid (8, 32, 4) = 1024 blocks, 32 chunks each.
// ---------------------------------------------------------------------------
#define K2A_OFF  4608
#define K2_STAGE 9728
#define K2_SMEM  29184

__device__ __forceinline__ void k2_issue(uint32_t sbase, const __half* xr,
                                         const __half* ar, int c, int tid) {
    if (c < Nn / NSPLIT / 32) {
        uint32_t st = sbase + (c % 3) * K2_STAGE;
        int n0 = c * 32;
#pragma unroll
        for (int p = 0; p < 2; p++) {
            int id = p * 128 + tid;
            int xrow = id >> 3, xsg = id & 7;
            CP16(st + xrow * 144 + xsg * 16,
                 xr + (size_t)(n0 + xrow) * Dd + xsg * 8);
            int arow = id >> 2, asg = id & 3;
            CP16(st + K2A_OFF + arow * 80 + asg * 16,
                 ar + (size_t)arow * Nn + n0 + asg * 8);
        }
    }
    CP_COMMIT();
}

__global__ __launch_bounds__(128) void k2_vlad()
{
    extern __shared__ __align__(16) char sm[];
    const uint32_t sbase = smem_u32(sm);

    const int tid  = threadIdx.x;
    const int lane = tid & 31;
    const int w    = tid >> 5;
    const int la   = lane >> 2;
    const int lb   = lane & 3;
    const int b    = blockIdx.y;
    const int d0   = blockIdx.x * 64;
    const int s    = blockIdx.z;
    const int nbase = s * (Nn / NSPLIT);

    const __half* xr = g_xh + ((size_t)(b * Nn + nbase)) * Dd + d0;
    const __half* ar = g_ah + ((size_t)(b * Kk)) * Nn + nbase;

    float acc[8][4];
#pragma unroll
    for (int j = 0; j < 8; j++)
#pragma unroll
        for (int q = 0; q < 4; q++) acc[j][q] = 0.0f;

    k2_issue(sbase, xr, ar, 0, tid);
    k2_issue(sbase, xr, ar, 1, tid);

    const int lq = lane >> 3, lr = lane & 7;
    const uint32_t xoff = ((lq >> 1) * 8 + lr) * 144 + (w * 16 + (lq & 1) * 8) * 2;

    const int L = Nn / NSPLIT / 32;
    for (int c = 0; c < L; c++) {
        __syncthreads();
        k2_issue(sbase, xr, ar, c + 2, tid);
        CP_WAIT2();
        __syncthreads();

        const uint32_t xbase = sbase + (c % 3) * K2_STAGE + xoff;
        const uint32_t* asA = (const uint32_t*)(sm + (c % 3) * K2_STAGE + K2A_OFF);
#pragma unroll
        for (int ss = 0; ss < 2; ss++) {
            uint32_t a0, a1, a2, a3;
            ldsm4t(a0, a1, a2, a3, xbase + ss * 16 * 144);
#pragma unroll
            for (int j = 0; j < 8; j++) {
                uint32_t b0 = asA[(j * 8 + la) * 20 + ss * 8 + lb];
                uint32_t b1 = asA[(j * 8 + la) * 20 + ss * 8 + 4 + lb];
                mma16(acc[j], a0, a1, a2, a3, b0, b1);
            }
        }
    }

    float* vp = g_vpart + ((size_t)s * Bb + b) * Kk * Dd;
    const int gdA = d0 + w * 16 + la;
    const int gdB = gdA + 8;
#pragma unroll
    for (int j = 0; j < 8; j++)
#pragma unroll
        for (int e = 0; e < 2; e++) {
            int col = j * 8 + lb * 2 + e;
            vp[(size_t)col * Dd + gdA] = acc[j][e];
            vp[(size_t)col * Dd + gdB] = acc[j][2 + e];
        }
}

// ---------------------------------------------------------------------------
// k3: sum 4 partial planes, subtract a_sum*clusters2, intra-normalize, out.
// ---------------------------------------------------------------------------
__global__ __launch_bounds__(128) void k3_colnorm(const float* __restrict__ c2,
                                                  float* __restrict__ out)
{
    const int bk = blockIdx.x;
    const int b = bk >> 6;
    const int k = bk & 63;
    const int tid = threadIdx.x;
    const size_t SP = (size_t)Bb * Kk * Dd;

    const float a = g_asum[bk];
    const float* vr = g_vpart + (size_t)bk * Dd;

    float v[4];
    float ss = 0.0f;
#pragma unroll
    for (int p = 0; p < 4; p++) {
        int d = tid + p * 128;
        float t = (vr[d] + vr[d + SP]) + (vr[d + 2 * SP] + vr[d + 3 * SP])
                - a * c2[(size_t)d * Kk + k];
        v[p] = t;
        ss += t * t;
    }
#pragma unroll
    for (int o = 16; o; o >>= 1) ss += __shfl_xor_sync(0xffffffffu, ss, o);

    __shared__ float sred[4];
    if ((tid & 31) == 0) sred[tid >> 5] = ss;
    __syncthreads();
    float tot = sred[0] + sred[1] + sred[2] + sred[3];
    float inv = 1.0f / fmaxf(sqrtf(tot), 1e-12f);
    if (tid == 0) atomicAdd(&g_gnormsq[b], tot * inv * inv);

    float* ob = out + (size_t)b * (Dd * Kk);
#pragma unroll
    for (int p = 0; p < 4; p++) {
        int d = tid + p * 128;
        ob[(size_t)d * Kk + k] = v[p] * inv;
    }
}

// ---------------------------------------------------------------------------
__global__ void k4_scale(float* __restrict__ out)
{
    int idx = blockIdx.x * 256 + threadIdx.x;
    int b = idx >> 15;
    out[idx] *= 1.0f / fmaxf(sqrtf(g_gnormsq[b]), 1e-12f);
}

// ---------------------------------------------------------------------------
extern "C" void kernel_launch(void* const* d_in, const int* in_sizes, int n_in,
                              void* d_out, int out_size)
{
    const float* x        = (const float*)d_in[0];
    const float* clusters = (const float*)d_in[1];
    const float* c2       = (const float*)d_in[2];
    const float* bnw      = (const float*)d_in[3];
    const float* bnb      = (const float*)d_in[4];
    const float* rm       = (const float*)d_in[5];
    const float* rv       = (const float*)d_in[6];
    float* out = (float*)d_out;

    cudaFuncSetAttribute(k1_logits_softmax,
                         cudaFuncAttributeMaxDynamicSharedMemorySize, K1_SMEM);

    k0_init<<<8, 256>>>();
    kC<<<32, 256>>>(clusters);
    k1_logits_softmax<<<(Bb * Nn) / 128, 256, K1_SMEM>>>(x, bnw, bnb, rm, rv);
    dim3 g2(Dd / 64, Bb, NSPLIT);
    k2_vlad<<<g2, 128, K2_SMEM>>>();
    k3_colnorm<<<Bb * Kk, 128>>>(c2, out);
    k4_scale<<<(Bb * Dd * Kk) / 256, 256>>>(out);
}